// round 1
// baseline (speedup 1.0000x reference)
#include <cuda_runtime.h>
#include <cuda_bf16.h>

// Problem constants
#define BB   16
#define CIN  128
#define COUT 128
#define HH   128
#define WW   128
#define SS   512
#define KK   9      // 3x3 taps

// Scratch (allocation-free: __device__ globals)
__device__ float d_s[BB * CIN];                       // modulation scalars [b][ci]
__device__ float d_wmod[BB * CIN * KK * COUT];        // demodulated weights [b][ci][k][co]

// ---------------------------------------------------------------------------
// Kernel A: s[b][ci] = sum_s style[b][s] * mod_w[ci][s] + mod_b[ci]
// grid = (B), block = (CIN)
// ---------------------------------------------------------------------------
__global__ void style_kernel(const float* __restrict__ style,
                             const float* __restrict__ mod_w,
                             const float* __restrict__ mod_b) {
    int b = blockIdx.x;
    int ci = threadIdx.x;
    __shared__ float st[SS];
    for (int i = threadIdx.x; i < SS; i += blockDim.x) st[i] = style[b * SS + i];
    __syncthreads();
    const float* mw = mod_w + ci * SS;
    float acc = 0.f;
#pragma unroll 8
    for (int i = 0; i < SS; i++) acc += st[i] * mw[i];
    d_s[b * CIN + ci] = acc + mod_b[ci];
}

// ---------------------------------------------------------------------------
// Kernel B: modulate + demodulate weights, store transposed [b][ci][k][co]
// grid = (B), block = (COUT); thread = co
// ---------------------------------------------------------------------------
__global__ void wprep_kernel(const float* __restrict__ weight) {
    int b = blockIdx.x;
    int co = threadIdx.x;
    __shared__ float sv[CIN];
    for (int i = threadIdx.x; i < CIN; i += blockDim.x) sv[i] = d_s[b * CIN + i];
    __syncthreads();

    const float* wco = weight + co * CIN * KK;  // weight[0][co][ci][kh][kw]
    float sumsq = 0.f;
    for (int ci = 0; ci < CIN; ci++) {
        float s = sv[ci];
#pragma unroll
        for (int k = 0; k < KK; k++) {
            float v = wco[ci * KK + k] * s;
            sumsq += v * v;
        }
    }
    float dc = rsqrtf(sumsq + 1e-8f);
    for (int ci = 0; ci < CIN; ci++) {
        float s = sv[ci] * dc;
#pragma unroll
        for (int k = 0; k < KK; k++) {
            d_wmod[((b * CIN + ci) * KK + k) * COUT + co] = wco[ci * KK + k] * s;
        }
    }
}

// ---------------------------------------------------------------------------
// Kernel C: direct conv. One block per (h, b). Block computes
// out[b, 0:128 co, h, 0:128 w]. 256 threads; each thread: 8co x 8w register tile.
// smem: 4-ci chunk of 3 padded x rows + [ci][9][co] weight slab.
// ---------------------------------------------------------------------------
#define CI_CHUNK 4
#define XROW 132   // 1 + 128 + 1 pad, rounded to mult of 4 floats (16B rows)

__global__ __launch_bounds__(256, 2)
void conv_kernel(const float* __restrict__ x, float* __restrict__ out) {
    __shared__ __align__(16) float xs[CI_CHUNK][3][XROW];
    __shared__ __align__(16) float ws[CI_CHUNK][KK][COUT];

    const int h = blockIdx.x;
    const int b = blockIdx.y;
    const int tid = (int)threadIdx.x;
    const int tco = tid >> 4;        // 0..15
    const int tw  = tid & 15;        // 0..15
    const int co0 = tco * 8;
    const int w0  = tw * 8;

    float acc[8][8];
#pragma unroll
    for (int i = 0; i < 8; i++)
#pragma unroll
        for (int j = 0; j < 8; j++) acc[i][j] = 0.f;

    const float* xb = x + (size_t)b * CIN * HH * WW;

    for (int ci0 = 0; ci0 < CIN; ci0 += CI_CHUNK) {
        __syncthreads();
        // --- load x chunk (3 rows per ci, padded, zero outside H) ---
        for (int idx = tid; idx < CI_CHUNK * 3 * WW; idx += 256) {
            int ci  = idx / (3 * WW);
            int rem = idx - ci * (3 * WW);
            int r   = rem / WW;
            int w   = rem - r * WW;
            int hh  = h + r - 1;
            float v = (hh >= 0 && hh < HH)
                      ? xb[(size_t)(ci0 + ci) * HH * WW + hh * WW + w] : 0.f;
            xs[ci][r][w + 1] = v;
        }
        if (tid < CI_CHUNK * 3) {
            int ci = tid / 3, r = tid % 3;
            xs[ci][r][0] = 0.f;
            xs[ci][r][WW + 1] = 0.f;
        }
        // --- load weight slab [ci][k][co], layout matches d_wmod → flat copy ---
        {
            const float* wm = d_wmod + ((size_t)b * CIN + ci0) * KK * COUT;
            float* wsf = &ws[0][0][0];
            for (int idx = tid; idx < CI_CHUNK * KK * COUT; idx += 256)
                wsf[idx] = wm[idx];
        }
        __syncthreads();

        // --- compute ---
#pragma unroll
        for (int ci = 0; ci < CI_CHUNK; ci++) {
#pragma unroll
            for (int kh = 0; kh < 3; kh++) {
                float xv[10];
                float4 xa = *(const float4*)&xs[ci][kh][w0];
                float4 xc = *(const float4*)&xs[ci][kh][w0 + 4];
                xv[0] = xa.x; xv[1] = xa.y; xv[2] = xa.z; xv[3] = xa.w;
                xv[4] = xc.x; xv[5] = xc.y; xv[6] = xc.z; xv[7] = xc.w;
                xv[8] = xs[ci][kh][w0 + 8];
                xv[9] = xs[ci][kh][w0 + 9];
#pragma unroll
                for (int kw = 0; kw < 3; kw++) {
                    float4 wa = *(const float4*)&ws[ci][kh * 3 + kw][co0];
                    float4 wb = *(const float4*)&ws[ci][kh * 3 + kw][co0 + 4];
                    float wr[8] = {wa.x, wa.y, wa.z, wa.w, wb.x, wb.y, wb.z, wb.w};
#pragma unroll
                    for (int i = 0; i < 8; i++)
#pragma unroll
                        for (int j = 0; j < 8; j++)
                            acc[i][j] += wr[i] * xv[j + kw];
                }
            }
        }
    }

    // --- write output: out[b][co][h][w] ---
#pragma unroll
    for (int i = 0; i < 8; i++) {
        float4 o0 = make_float4(acc[i][0], acc[i][1], acc[i][2], acc[i][3]);
        float4 o1 = make_float4(acc[i][4], acc[i][5], acc[i][6], acc[i][7]);
        size_t base = (((size_t)b * COUT + (co0 + i)) * HH + h) * WW + w0;
        *(float4*)&out[base]     = o0;
        *(float4*)&out[base + 4] = o1;
    }
}

// ---------------------------------------------------------------------------
// Launch
// ---------------------------------------------------------------------------
extern "C" void kernel_launch(void* const* d_in, const int* in_sizes, int n_in,
                              void* d_out, int out_size) {
    const float* x      = (const float*)d_in[0];  // [16,128,128,128]
    const float* style  = (const float*)d_in[1];  // [16,512]
    const float* weight = (const float*)d_in[2];  // [1,128,128,3,3]
    const float* mod_w  = (const float*)d_in[3];  // [128,512]
    const float* mod_b  = (const float*)d_in[4];  // [128]
    float* out = (float*)d_out;                   // [16,128,128,128]

    style_kernel<<<BB, CIN>>>(style, mod_w, mod_b);
    wprep_kernel<<<BB, COUT>>>(weight);
    dim3 grid(HH, BB);
    conv_kernel<<<grid, 256>>>(x, out);
}

// round 2
// speedup vs baseline: 1.0024x; 1.0024x over previous
#include <cuda_runtime.h>
#include <cuda_bf16.h>

// Problem constants
#define BB   16
#define CIN  128
#define COUT 128
#define HH   128
#define WW   128
#define SS   512
#define KK   9      // 3x3 taps

// Scratch (allocation-free: __device__ globals)
__device__ float d_s[BB * CIN];                       // modulation scalars [b][ci]
__device__ float d_wmod[BB * CIN * KK * COUT];        // demodulated weights [b][ci][k][co]

// ---------------------------------------------------------------------------
// Kernel A: s[b][ci] = sum_s style[b][s] * mod_w[ci][s] + mod_b[ci]
// grid = (B), block = (CIN)
// ---------------------------------------------------------------------------
__global__ void style_kernel(const float* __restrict__ style,
                             const float* __restrict__ mod_w,
                             const float* __restrict__ mod_b) {
    int b = blockIdx.x;
    int ci = threadIdx.x;
    __shared__ float st[SS];
    for (int i = threadIdx.x; i < SS; i += blockDim.x) st[i] = style[b * SS + i];
    __syncthreads();
    const float* mw = mod_w + ci * SS;
    float acc = 0.f;
#pragma unroll 8
    for (int i = 0; i < SS; i++) acc += st[i] * mw[i];
    d_s[b * CIN + ci] = acc + mod_b[ci];
}

// ---------------------------------------------------------------------------
// Kernel B: modulate + demodulate weights, store transposed [b][ci][k][co]
// grid = (B), block = (COUT); thread = co
// ---------------------------------------------------------------------------
__global__ void wprep_kernel(const float* __restrict__ weight) {
    int b = blockIdx.x;
    int co = threadIdx.x;
    __shared__ float sv[CIN];
    for (int i = threadIdx.x; i < CIN; i += blockDim.x) sv[i] = d_s[b * CIN + i];
    __syncthreads();

    const float* wco = weight + co * CIN * KK;  // weight[0][co][ci][kh][kw]
    float sumsq = 0.f;
    for (int ci = 0; ci < CIN; ci++) {
        float s = sv[ci];
#pragma unroll
        for (int k = 0; k < KK; k++) {
            float v = wco[ci * KK + k] * s;
            sumsq += v * v;
        }
    }
    float dc = rsqrtf(sumsq + 1e-8f);
    for (int ci = 0; ci < CIN; ci++) {
        float s = sv[ci] * dc;
#pragma unroll
        for (int k = 0; k < KK; k++) {
            d_wmod[((b * CIN + ci) * KK + k) * COUT + co] = wco[ci * KK + k] * s;
        }
    }
}

// ---------------------------------------------------------------------------
// Kernel C: direct conv. One block per (h, b). Block computes
// out[b, 0:128 co, h, 0:128 w]. 256 threads; each thread: 8co x 8w register tile.
// smem: 4-ci chunk of 3 padded x rows + [ci][9][co] weight slab.
// ---------------------------------------------------------------------------
#define CI_CHUNK 4
#define XROW 132   // 1 + 128 + 1 pad, rounded to mult of 4 floats (16B rows)

__global__ __launch_bounds__(256, 2)
void conv_kernel(const float* __restrict__ x, float* __restrict__ out) {
    __shared__ __align__(16) float xs[CI_CHUNK][3][XROW];
    __shared__ __align__(16) float ws[CI_CHUNK][KK][COUT];

    const int h = blockIdx.x;
    const int b = blockIdx.y;
    const int tid = (int)threadIdx.x;
    const int tco = tid >> 4;        // 0..15
    const int tw  = tid & 15;        // 0..15
    const int co0 = tco * 8;
    const int w0  = tw * 8;

    float acc[8][8];
#pragma unroll
    for (int i = 0; i < 8; i++)
#pragma unroll
        for (int j = 0; j < 8; j++) acc[i][j] = 0.f;

    const float* xb = x + (size_t)b * CIN * HH * WW;

    for (int ci0 = 0; ci0 < CIN; ci0 += CI_CHUNK) {
        __syncthreads();
        // --- load x chunk (3 rows per ci, padded, zero outside H) ---
        for (int idx = tid; idx < CI_CHUNK * 3 * WW; idx += 256) {
            int ci  = idx / (3 * WW);
            int rem = idx - ci * (3 * WW);
            int r   = rem / WW;
            int w   = rem - r * WW;
            int hh  = h + r - 1;
            float v = (hh >= 0 && hh < HH)
                      ? xb[(size_t)(ci0 + ci) * HH * WW + hh * WW + w] : 0.f;
            xs[ci][r][w + 1] = v;
        }
        if (tid < CI_CHUNK * 3) {
            int ci = tid / 3, r = tid % 3;
            xs[ci][r][0] = 0.f;
            xs[ci][r][WW + 1] = 0.f;
        }
        // --- load weight slab [ci][k][co], layout matches d_wmod → flat copy ---
        {
            const float* wm = d_wmod + ((size_t)b * CIN + ci0) * KK * COUT;
            float* wsf = &ws[0][0][0];
            for (int idx = tid; idx < CI_CHUNK * KK * COUT; idx += 256)
                wsf[idx] = wm[idx];
        }
        __syncthreads();

        // --- compute ---
#pragma unroll
        for (int ci = 0; ci < CI_CHUNK; ci++) {
#pragma unroll
            for (int kh = 0; kh < 3; kh++) {
                float xv[10];
                float4 xa = *(const float4*)&xs[ci][kh][w0];
                float4 xc = *(const float4*)&xs[ci][kh][w0 + 4];
                xv[0] = xa.x; xv[1] = xa.y; xv[2] = xa.z; xv[3] = xa.w;
                xv[4] = xc.x; xv[5] = xc.y; xv[6] = xc.z; xv[7] = xc.w;
                xv[8] = xs[ci][kh][w0 + 8];
                xv[9] = xs[ci][kh][w0 + 9];
#pragma unroll
                for (int kw = 0; kw < 3; kw++) {
                    float4 wa = *(const float4*)&ws[ci][kh * 3 + kw][co0];
                    float4 wb = *(const float4*)&ws[ci][kh * 3 + kw][co0 + 4];
                    float wr[8] = {wa.x, wa.y, wa.z, wa.w, wb.x, wb.y, wb.z, wb.w};
#pragma unroll
                    for (int i = 0; i < 8; i++)
#pragma unroll
                        for (int j = 0; j < 8; j++)
                            acc[i][j] += wr[i] * xv[j + kw];
                }
            }
        }
    }

    // --- write output: out[b][co][h][w] ---
#pragma unroll
    for (int i = 0; i < 8; i++) {
        float4 o0 = make_float4(acc[i][0], acc[i][1], acc[i][2], acc[i][3]);
        float4 o1 = make_float4(acc[i][4], acc[i][5], acc[i][6], acc[i][7]);
        size_t base = (((size_t)b * COUT + (co0 + i)) * HH + h) * WW + w0;
        *(float4*)&out[base]     = o0;
        *(float4*)&out[base + 4] = o1;
    }
}

// ---------------------------------------------------------------------------
// Launch
// ---------------------------------------------------------------------------
extern "C" void kernel_launch(void* const* d_in, const int* in_sizes, int n_in,
                              void* d_out, int out_size) {
    const float* x      = (const float*)d_in[0];  // [16,128,128,128]
    const float* style  = (const float*)d_in[1];  // [16,512]
    const float* weight = (const float*)d_in[2];  // [1,128,128,3,3]
    const float* mod_w  = (const float*)d_in[3];  // [128,512]
    const float* mod_b  = (const float*)d_in[4];  // [128]
    float* out = (float*)d_out;                   // [16,128,128,128]

    style_kernel<<<BB, CIN>>>(style, mod_w, mod_b);
    wprep_kernel<<<BB, COUT>>>(weight);
    dim3 grid(HH, BB);
    conv_kernel<<<grid, 256>>>(x, out);
}

// round 9
// speedup vs baseline: 5.0839x; 5.0719x over previous
#include <cuda_runtime.h>
#include <cuda_fp16.h>
#include <cstdint>
#include <cstddef>

#define BB   16
#define CIN  128
#define COUT 128
#define HH   128
#define WW   128
#define SS   512

// ---------------- device scratch (allocation-free) ----------------
__device__ float d_s[BB * CIN];       // modulation scalars [b][ci]
__device__ float d_q[COUT * CIN];     // sum_k w^2 per (co,ci)
__device__ float d_dc[BB * COUT];     // demod coefficients
// Pre-modulated fp16 A tiles: [b][stage(12)] blocks of 128 co x 104 halfs (96 k + 8 pad)
__device__ __align__(16) __half d_wA[BB * 12 * 128 * 104];

__device__ __forceinline__ uint32_t smem_u32(const void* p) {
    uint32_t a;
    asm("{ .reg .u64 t; cvta.to.shared.u64 t, %1; cvt.u32.u64 %0, t; }" : "=r"(a) : "l"(p));
    return a;
}

#define LDSM4(r, a) \
    asm volatile("ldmatrix.sync.aligned.m8n8.x4.shared.b16 {%0,%1,%2,%3}, [%4];" \
        : "=r"((r)[0]), "=r"((r)[1]), "=r"((r)[2]), "=r"((r)[3]) : "r"(a))
#define LDSM4T(r, a) \
    asm volatile("ldmatrix.sync.aligned.m8n8.x4.trans.shared.b16 {%0,%1,%2,%3}, [%4];" \
        : "=r"((r)[0]), "=r"((r)[1]), "=r"((r)[2]), "=r"((r)[3]) : "r"(a))

__device__ __forceinline__ void mma16816(float* c, const uint32_t* a, uint32_t b0, uint32_t b1) {
    asm volatile(
        "mma.sync.aligned.m16n8k16.row.col.f32.f16.f16.f32 "
        "{%0,%1,%2,%3}, {%4,%5,%6,%7}, {%8,%9}, {%0,%1,%2,%3};"
        : "+f"(c[0]), "+f"(c[1]), "+f"(c[2]), "+f"(c[3])
        : "r"(a[0]), "r"(a[1]), "r"(a[2]), "r"(a[3]), "r"(b0), "r"(b1));
}

// ---------------- prep kernels ----------------
__global__ void k_style(const float* __restrict__ style, const float* __restrict__ mod_w,
                        const float* __restrict__ mod_b) {
    int task = blockIdx.x * 8 + (threadIdx.x >> 5);   // (b,ci), 2048 warps
    int lane = threadIdx.x & 31;
    int b = task >> 7, ci = task & 127;
    const float* st = style + b * SS;
    const float* mw = mod_w + ci * SS;
    float a = 0.f;
    for (int i = lane; i < SS; i += 32) a += st[i] * mw[i];
#pragma unroll
    for (int o = 16; o; o >>= 1) a += __shfl_xor_sync(0xffffffffu, a, o);
    if (lane == 0) d_s[task] = a + mod_b[ci];
}

__global__ void k_q(const float* __restrict__ weight) {
    int i = blockIdx.x * 256 + threadIdx.x;           // (co,ci), 16384
    const float* w = weight + (size_t)i * 9;
    float s = 0.f;
#pragma unroll
    for (int k = 0; k < 9; k++) { float v = w[k]; s += v * v; }
    d_q[i] = s;
}

__global__ void k_dc() {
    int task = blockIdx.x * 8 + (threadIdx.x >> 5);   // (b,co), 2048 warps
    int lane = threadIdx.x & 31;
    int b = task >> 7, co = task & 127;
    float a = 0.f;
    for (int ci = lane; ci < 128; ci += 32) {
        float s = d_s[b * 128 + ci];
        a += d_q[co * 128 + ci] * s * s;
    }
#pragma unroll
    for (int o = 16; o; o >>= 1) a += __shfl_xor_sync(0xffffffffu, a, o);
    if (lane == 0) d_dc[task] = rsqrtf(a + 1e-8f);
}

// Pack modulated weights: stage st = kh*4 + chunk; k = ci_local*3 + kw (96, pad to 104)
__global__ void k_wprep(const float* __restrict__ weight) {
    int b = blockIdx.x;          // 16
    int st = blockIdx.y;         // 12
    int kh = st >> 2, chunk = st & 3, ci0 = chunk * 32;
    __half* dst = d_wA + (size_t)(b * 12 + st) * 13312;
    for (int idx = threadIdx.x; idx < 13312; idx += 256) {
        int co = idx / 104, kk = idx % 104;
        __half v = __ushort_as_half(0);
        if (kk < 96) {
            int cil = kk / 3, kw = kk - cil * 3;
            int ci = ci0 + cil;
            float val = weight[(size_t)(co * 128 + ci) * 9 + kh * 3 + kw]
                        * d_s[b * 128 + ci] * d_dc[b * 128 + co];
            v = __float2half_rn(val);
        }
        dst[idx] = v;
    }
}

// ---------------- main conv kernel ----------------
// smem: A [128 co][104 halfs] = 26624 B; B [96 k][136 halfs] = 26112 B
#define SM_A 0
#define SM_B 26624
#define SMEM_BYTES 52736

__global__ void __launch_bounds__(256) k_conv(const float* __restrict__ x,
                                              float* __restrict__ out) {
    extern __shared__ char smem[];
    uint32_t sb = smem_u32(smem);
    const int tid  = threadIdx.x;
    const int wid  = tid >> 5, lane = tid & 31;
    const int h = blockIdx.x, b = blockIdx.y;
    const int m0w = (wid & 3) * 32;     // warp m origin (co)
    const int n0w = (wid >> 2) * 64;    // warp n origin (w)

    float acc[2][8][4];
#pragma unroll
    for (int i = 0; i < 2; i++)
#pragma unroll
        for (int j = 0; j < 8; j++)
#pragma unroll
            for (int kq = 0; kq < 4; kq++) acc[i][j][kq] = 0.f;

    const float* xb = x + (size_t)b * CIN * HH * WW;
    const int ci_t = tid >> 3;   // 0..31 (ci within chunk for B build)
    const int sv   = tid & 7;

    // ldmatrix per-thread base addresses
    const uint32_t a_base = sb + SM_A + (uint32_t)(m0w + (lane & 15)) * 208
                            + (uint32_t)(lane >> 4) * 16;
    const uint32_t b_base = sb + SM_B + (uint32_t)(lane & 15) * 272
                            + (uint32_t)(n0w + (lane >> 4) * 8) * 2;

    for (int st = 0; st < 12; st++) {
        const int kh = st >> 2, chunk = st & 3;
        if (st) __syncthreads();

        // ---- A: flat copy of pre-packed fp16 weights (26624 B) ----
        {
            const uint4* asrc = (const uint4*)(d_wA + (size_t)(b * 12 + st) * 13312);
            for (int i = tid; i < 1664; i += 256)
                *(uint4*)(smem + SM_A + (size_t)i * 16) = asrc[i];
        }
        // ---- B: im2col, 3 shifted copies per ci row ----
        {
            const int hh = h + kh - 1;
            const bool rv = (hh >= 0) && (hh < HH);
            const float* xr = xb + ((size_t)(chunk * 32 + ci_t) * HH + (rv ? hh : 0)) * WW;
            const uint32_t brow = sb + SM_B + (uint32_t)(ci_t * 3) * 272;
#pragma unroll
            for (int i = 0; i < 17; i++) {
                int v = sv + 8 * i;           // 0..129 -> input w = v-1
                if (v < 130) {
                    int w = v - 1;
                    float f = 0.f;
                    if (rv && w >= 0 && w < WW) f = __ldg(xr + w);
                    unsigned short hv = __half_as_ushort(__float2half_rn(f));
#pragma unroll
                    for (int kw = 0; kw < 3; kw++) {
                        int n = v - kw;
                        if (n >= 0 && n < 128) {
                            uint32_t addr = brow + (uint32_t)kw * 272 + (uint32_t)(2 * n);
                            asm volatile("st.shared.b16 [%0], %1;" :: "r"(addr), "h"(hv));
                        }
                    }
                }
            }
        }
        __syncthreads();

        // ---- compute: 6 k-steps of m16n8k16 ----
#pragma unroll
        for (int ks = 0; ks < 6; ks++) {
            uint32_t a0[4], a1[4], bf[4][4];
            LDSM4(a0, a_base + (uint32_t)ks * 32);
            LDSM4(a1, a_base + (uint32_t)ks * 32 + 16u * 208u);
#pragma unroll
            for (int nb = 0; nb < 4; nb++)
                LDSM4T(bf[nb], b_base + (uint32_t)ks * 16u * 272u + (uint32_t)nb * 32u);
#pragma unroll
            for (int mt = 0; mt < 2; mt++) {
                const uint32_t* a = mt ? a1 : a0;
#pragma unroll
                for (int nk = 0; nk < 8; nk++) {
                    uint32_t bb0 = bf[nk >> 1][(nk & 1) * 2];
                    uint32_t bb1 = bf[nk >> 1][(nk & 1) * 2 + 1];
                    mma16816(acc[mt][nk], a, bb0, bb1);
                }
            }
        }
    }

    // ---- epilogue ----
#pragma unroll
    for (int mt = 0; mt < 2; mt++) {
        int m_lo = m0w + mt * 16 + (lane >> 2);
#pragma unroll
        for (int nk = 0; nk < 8; nk++) {
            int n = n0w + nk * 8 + (lane & 3) * 2;
            float2 v0 = make_float2(acc[mt][nk][0], acc[mt][nk][1]);
            float2 v1 = make_float2(acc[mt][nk][2], acc[mt][nk][3]);
            *(float2*)(out + (((size_t)b * 128 + m_lo) * 128 + h) * 128 + n)     = v0;
            *(float2*)(out + (((size_t)b * 128 + m_lo + 8) * 128 + h) * 128 + n) = v1;
        }
    }
}

// ---------------- launch ----------------
extern "C" void kernel_launch(void* const* d_in, const int* in_sizes, int n_in,
                              void* d_out, int out_size) {
    const float* x      = (const float*)d_in[0];
    const float* style  = (const float*)d_in[1];
    const float* weight = (const float*)d_in[2];
    const float* mod_w  = (const float*)d_in[3];
    const float* mod_b  = (const float*)d_in[4];
    float* out = (float*)d_out;

    cudaFuncSetAttribute(k_conv, cudaFuncAttributeMaxDynamicSharedMemorySize, SMEM_BYTES);

    k_style<<<256, 256>>>(style, mod_w, mod_b);
    k_q<<<64, 256>>>(weight);
    k_dc<<<256, 256>>>();
    k_wprep<<<dim3(16, 12), 256>>>(weight);
    dim3 grid(HH, BB);
    k_conv<<<grid, 256, SMEM_BYTES>>>(x, out);
}

// round 11
// speedup vs baseline: 7.1077x; 1.3981x over previous
#include <cuda_runtime.h>
#include <cuda_fp16.h>
#include <cstdint>
#include <cstddef>

#define BB   16
#define CIN  128
#define COUT 128
#define HH   128
#define WW   128
#define SS   512

// ---------------- device scratch (allocation-free) ----------------
__device__ float d_s[BB * CIN];       // modulation scalars [b][ci]
__device__ float d_q[COUT * CIN];     // sum_k w^2 per (co,ci)
__device__ float d_dc[BB * COUT];     // demod coefficients
// Pre-modulated fp16 A tiles: [b][stage(12)] blocks of 128 co x 104 halfs (96 k + 8 pad)
__device__ __align__(16) __half d_wA[BB * 12 * 128 * 104];

__device__ __forceinline__ uint32_t smem_u32(const void* p) {
    uint32_t a;
    asm("{ .reg .u64 t; cvta.to.shared.u64 t, %1; cvt.u32.u64 %0, t; }" : "=r"(a) : "l"(p));
    return a;
}

#define LDSM4(r, a) \
    asm volatile("ldmatrix.sync.aligned.m8n8.x4.shared.b16 {%0,%1,%2,%3}, [%4];" \
        : "=r"((r)[0]), "=r"((r)[1]), "=r"((r)[2]), "=r"((r)[3]) : "r"(a))
#define LDSM4T(r, a) \
    asm volatile("ldmatrix.sync.aligned.m8n8.x4.trans.shared.b16 {%0,%1,%2,%3}, [%4];" \
        : "=r"((r)[0]), "=r"((r)[1]), "=r"((r)[2]), "=r"((r)[3]) : "r"(a))

__device__ __forceinline__ void mma16816(float* c, const uint32_t* a, uint32_t b0, uint32_t b1) {
    asm volatile(
        "mma.sync.aligned.m16n8k16.row.col.f32.f16.f16.f32 "
        "{%0,%1,%2,%3}, {%4,%5,%6,%7}, {%8,%9}, {%0,%1,%2,%3};"
        : "+f"(c[0]), "+f"(c[1]), "+f"(c[2]), "+f"(c[3])
        : "r"(a[0]), "r"(a[1]), "r"(a[2]), "r"(a[3]), "r"(b0), "r"(b1));
}

#define CP_ASYNC16(dst, src) \
    asm volatile("cp.async.cg.shared.global [%0], [%1], 16;" :: "r"(dst), "l"(src))
#define CP_COMMIT() asm volatile("cp.async.commit_group;" ::: "memory")
#define CP_WAIT0()  asm volatile("cp.async.wait_group 0;" ::: "memory")

// ---------------- prep kernels ----------------
__global__ void k_style(const float* __restrict__ style, const float* __restrict__ mod_w,
                        const float* __restrict__ mod_b) {
    int task = blockIdx.x * 8 + (threadIdx.x >> 5);   // (b,ci), 2048 warps
    int lane = threadIdx.x & 31;
    int b = task >> 7, ci = task & 127;
    const float* st = style + b * SS;
    const float* mw = mod_w + ci * SS;
    float a = 0.f;
    for (int i = lane; i < SS; i += 32) a += st[i] * mw[i];
#pragma unroll
    for (int o = 16; o; o >>= 1) a += __shfl_xor_sync(0xffffffffu, a, o);
    if (lane == 0) d_s[task] = a + mod_b[ci];
}

__global__ void k_q(const float* __restrict__ weight) {
    int i = blockIdx.x * 256 + threadIdx.x;           // (co,ci), 16384
    const float* w = weight + (size_t)i * 9;
    float s = 0.f;
#pragma unroll
    for (int k = 0; k < 9; k++) { float v = w[k]; s += v * v; }
    d_q[i] = s;
}

__global__ void k_dc() {
    int task = blockIdx.x * 8 + (threadIdx.x >> 5);   // (b,co), 2048 warps
    int lane = threadIdx.x & 31;
    int b = task >> 7, co = task & 127;
    float a = 0.f;
    for (int ci = lane; ci < 128; ci += 32) {
        float s = d_s[b * 128 + ci];
        a += d_q[co * 128 + ci] * s * s;
    }
#pragma unroll
    for (int o = 16; o; o >>= 1) a += __shfl_xor_sync(0xffffffffu, a, o);
    if (lane == 0) d_dc[task] = rsqrtf(a + 1e-8f);
}

// Pack modulated weights: stage st = kh*4 + chunk; k = ci_local*3 + kw (96, pad to 104)
// grid (16, 12, 4): each block handles 32 co
__global__ void k_wprep(const float* __restrict__ weight) {
    int b = blockIdx.x;          // 16
    int st = blockIdx.y;         // 12
    int co0 = blockIdx.z * 32;   // 4 chunks of 32 co
    int kh = st >> 2, chunk = st & 3, ci0 = chunk * 32;
    __half* dst = d_wA + (size_t)(b * 12 + st) * 13312 + (size_t)co0 * 104;
    for (int idx = threadIdx.x; idx < 32 * 104; idx += 256) {
        int co = co0 + idx / 104, kk = idx % 104;
        __half v = __ushort_as_half(0);
        if (kk < 96) {
            int cil = kk / 3, kw = kk - cil * 3;
            int ci = ci0 + cil;
            float val = __ldg(weight + (size_t)(co * 128 + ci) * 9 + kh * 3 + kw)
                        * d_s[b * 128 + ci] * d_dc[b * 128 + co];
            v = __float2half_rn(val);
        }
        dst[idx] = v;
    }
}

// ---------------- main conv kernel ----------------
// smem: A [128 co][104 halfs] = 26624 B; B [96 k][136 halfs] = 26112 B
#define SM_A 0
#define SM_B 26624
#define SMEM_BYTES 52736

__global__ void __launch_bounds__(256, 2) k_conv(const float* __restrict__ x,
                                                 float* __restrict__ out) {
    extern __shared__ char smem[];
    uint32_t sb = smem_u32(smem);
    const int tid  = threadIdx.x;
    const int wid  = tid >> 5, lane = tid & 31;
    const int h = blockIdx.x, b = blockIdx.y;
    const int m0w = (wid & 3) * 32;     // warp m origin (co)
    const int n0w = (wid >> 2) * 64;    // warp n origin (w)

    float acc[2][8][4];
#pragma unroll
    for (int i = 0; i < 2; i++)
#pragma unroll
        for (int j = 0; j < 8; j++)
#pragma unroll
            for (int kq = 0; kq < 4; kq++) acc[i][j][kq] = 0.f;

    const float* xb = x + (size_t)b * CIN * HH * WW;
    const int ci_t = tid >> 3;   // 0..31 (ci within chunk for B build)
    const int sv   = tid & 7;

    // ldmatrix per-thread base addresses
    const uint32_t a_base = sb + SM_A + (uint32_t)(m0w + (lane & 15)) * 208
                            + (uint32_t)(lane >> 4) * 16;
    const uint32_t b_base = sb + SM_B + (uint32_t)(lane & 15) * 272
                            + (uint32_t)(n0w + (lane >> 4) * 8) * 2;

    for (int st = 0; st < 12; st++) {
        const int kh = st >> 2, chunk = st & 3;
        if (st) __syncthreads();

        // ---- A: async copy of pre-packed fp16 weights (26624 B) ----
        {
            const char* asrc = (const char*)(d_wA + (size_t)(b * 12 + st) * 13312);
#pragma unroll
            for (int i = 0; i < 7; i++) {
                int e = tid + i * 256;
                if (e < 1664)
                    CP_ASYNC16(sb + SM_A + (uint32_t)e * 16, asrc + (size_t)e * 16);
            }
            CP_COMMIT();
        }
        // ---- B: im2col, 3 shifted copies per ci row ----
        {
            const int hh = h + kh - 1;
            const bool rv = (hh >= 0) && (hh < HH);
            const float* xr = xb + ((size_t)(chunk * 32 + ci_t) * HH + (rv ? hh : 0)) * WW;
            const uint32_t brow = sb + SM_B + (uint32_t)(ci_t * 3) * 272;
#pragma unroll
            for (int i = 0; i < 17; i++) {
                int v = sv + 8 * i;           // 0..129 -> input w = v-1
                if (v < 130) {
                    int w = v - 1;
                    float f = 0.f;
                    if (rv && w >= 0 && w < WW) f = __ldg(xr + w);
                    unsigned short hv = __half_as_ushort(__float2half_rn(f));
#pragma unroll
                    for (int kw = 0; kw < 3; kw++) {
                        int n = v - kw;
                        if (n >= 0 && n < 128) {
                            uint32_t addr = brow + (uint32_t)kw * 272 + (uint32_t)(2 * n);
                            asm volatile("st.shared.b16 [%0], %1;" :: "r"(addr), "h"(hv));
                        }
                    }
                }
            }
        }
        CP_WAIT0();
        __syncthreads();

        // ---- compute: 6 k-steps of m16n8k16 ----
#pragma unroll
        for (int ks = 0; ks < 6; ks++) {
            uint32_t a0[4], a1[4], bf[4][4];
            LDSM4(a0, a_base + (uint32_t)ks * 32);
            LDSM4(a1, a_base + (uint32_t)ks * 32 + 16u * 208u);
#pragma unroll
            for (int nb = 0; nb < 4; nb++)
                LDSM4T(bf[nb], b_base + (uint32_t)ks * 16u * 272u + (uint32_t)nb * 32u);
#pragma unroll
            for (int mt = 0; mt < 2; mt++) {
                const uint32_t* a = mt ? a1 : a0;
#pragma unroll
                for (int nk = 0; nk < 8; nk++) {
                    uint32_t bb0 = bf[nk >> 1][(nk & 1) * 2];
                    uint32_t bb1 = bf[nk >> 1][(nk & 1) * 2 + 1];
                    mma16816(acc[mt][nk], a, bb0, bb1);
                }
            }
        }
    }

    // ---- epilogue ----
#pragma unroll
    for (int mt = 0; mt < 2; mt++) {
        int m_lo = m0w + mt * 16 + (lane >> 2);
#pragma unroll
        for (int nk = 0; nk < 8; nk++) {
            int n = n0w + nk * 8 + (lane & 3) * 2;
            float2 v0 = make_float2(acc[mt][nk][0], acc[mt][nk][1]);
            float2 v1 = make_float2(acc[mt][nk][2], acc[mt][nk][3]);
            *(float2*)(out + (((size_t)b * 128 + m_lo) * 128 + h) * 128 + n)     = v0;
            *(float2*)(out + (((size_t)b * 128 + m_lo + 8) * 128 + h) * 128 + n) = v1;
        }
    }
}

// ---------------- launch ----------------
extern "C" void kernel_launch(void* const* d_in, const int* in_sizes, int n_in,
                              void* d_out, int out_size) {
    const float* x      = (const float*)d_in[0];
    const float* style  = (const float*)d_in[1];
    const float* weight = (const float*)d_in[2];
    const float* mod_w  = (const float*)d_in[3];
    const float* mod_b  = (const float*)d_in[4];
    float* out = (float*)d_out;

    cudaFuncSetAttribute(k_conv, cudaFuncAttributeMaxDynamicSharedMemorySize, SMEM_BYTES);

    k_style<<<256, 256>>>(style, mod_w, mod_b);
    k_q<<<64, 256>>>(weight);
    k_dc<<<256, 256>>>();
    k_wprep<<<dim3(16, 12, 4), 256>>>(weight);
    dim3 grid(HH, BB);
    k_conv<<<grid, 256, SMEM_BYTES>>>(x, out);
}

// round 12
// speedup vs baseline: 7.1280x; 1.0029x over previous
#include <cuda_runtime.h>
#include <cuda_fp16.h>
#include <cstdint>
#include <cstddef>

#define BB   16
#define CIN  128
#define COUT 128
#define HH   128
#define WW   128
#define SS   512

// ---------------- device scratch (allocation-free) ----------------
__device__ float d_s[BB * CIN];       // modulation scalars [b][ci]
__device__ float d_q[COUT * CIN];     // sum_k w^2 per (co,ci)
__device__ float d_dc[BB * COUT];     // demod coefficients
// Pre-modulated fp16 A tiles: [b][stage(12)] blocks of 128 co x 104 halfs (96 k + 8 pad)
__device__ __align__(16) __half d_wA[BB * 12 * 128 * 104];

__device__ __forceinline__ uint32_t smem_u32(const void* p) {
    uint32_t a;
    asm("{ .reg .u64 t; cvta.to.shared.u64 t, %1; cvt.u32.u64 %0, t; }" : "=r"(a) : "l"(p));
    return a;
}

#define LDSM4(r, a) \
    asm volatile("ldmatrix.sync.aligned.m8n8.x4.shared.b16 {%0,%1,%2,%3}, [%4];" \
        : "=r"((r)[0]), "=r"((r)[1]), "=r"((r)[2]), "=r"((r)[3]) : "r"(a))
#define LDSM4T(r, a) \
    asm volatile("ldmatrix.sync.aligned.m8n8.x4.trans.shared.b16 {%0,%1,%2,%3}, [%4];" \
        : "=r"((r)[0]), "=r"((r)[1]), "=r"((r)[2]), "=r"((r)[3]) : "r"(a))

__device__ __forceinline__ void mma16816(float* c, const uint32_t* a, uint32_t b0, uint32_t b1) {
    asm volatile(
        "mma.sync.aligned.m16n8k16.row.col.f32.f16.f16.f32 "
        "{%0,%1,%2,%3}, {%4,%5,%6,%7}, {%8,%9}, {%0,%1,%2,%3};"
        : "+f"(c[0]), "+f"(c[1]), "+f"(c[2]), "+f"(c[3])
        : "r"(a[0]), "r"(a[1]), "r"(a[2]), "r"(a[3]), "r"(b0), "r"(b1));
}

#define CP_ASYNC16(dst, src) \
    asm volatile("cp.async.cg.shared.global [%0], [%1], 16;" :: "r"(dst), "l"(src))
#define CP_COMMIT() asm volatile("cp.async.commit_group;" ::: "memory")
#define CP_WAIT0()  asm volatile("cp.async.wait_group 0;" ::: "memory")

// ---------------- prep kernels ----------------
__global__ void k_style(const float* __restrict__ style, const float* __restrict__ mod_w,
                        const float* __restrict__ mod_b) {
    int task = blockIdx.x * 8 + (threadIdx.x >> 5);   // (b,ci), 2048 warps
    int lane = threadIdx.x & 31;
    int b = task >> 7, ci = task & 127;
    const float* st = style + b * SS;
    const float* mw = mod_w + ci * SS;
    float a = 0.f;
    for (int i = lane; i < SS; i += 32) a += st[i] * mw[i];
#pragma unroll
    for (int o = 16; o; o >>= 1) a += __shfl_xor_sync(0xffffffffu, a, o);
    if (lane == 0) d_s[task] = a + mod_b[ci];
}

__global__ void k_q(const float* __restrict__ weight) {
    int i = blockIdx.x * 256 + threadIdx.x;           // (co,ci), 16384
    const float* w = weight + (size_t)i * 9;
    float s = 0.f;
#pragma unroll
    for (int k = 0; k < 9; k++) { float v = w[k]; s += v * v; }
    d_q[i] = s;
}

__global__ void k_dc() {
    int task = blockIdx.x * 8 + (threadIdx.x >> 5);   // (b,co), 2048 warps
    int lane = threadIdx.x & 31;
    int b = task >> 7, co = task & 127;
    float a = 0.f;
    for (int ci = lane; ci < 128; ci += 32) {
        float s = d_s[b * 128 + ci];
        a += d_q[co * 128 + ci] * s * s;
    }
#pragma unroll
    for (int o = 16; o; o >>= 1) a += __shfl_xor_sync(0xffffffffu, a, o);
    if (lane == 0) d_dc[task] = rsqrtf(a + 1e-8f);
}

// Pack modulated weights: stage st = kh*4 + chunk; k = ci_local*3 + kw (96, pad to 104)
// grid (16, 12, 4): each block handles 32 co
__global__ void k_wprep(const float* __restrict__ weight) {
    int b = blockIdx.x;          // 16
    int st = blockIdx.y;         // 12
    int co0 = blockIdx.z * 32;   // 4 chunks of 32 co
    int kh = st >> 2, chunk = st & 3, ci0 = chunk * 32;
    __half* dst = d_wA + (size_t)(b * 12 + st) * 13312 + (size_t)co0 * 104;
    for (int idx = threadIdx.x; idx < 32 * 104; idx += 256) {
        int co = co0 + idx / 104, kk = idx % 104;
        __half v = __ushort_as_half(0);
        if (kk < 96) {
            int cil = kk / 3, kw = kk - cil * 3;
            int ci = ci0 + cil;
            float val = __ldg(weight + (size_t)(co * 128 + ci) * 9 + kh * 3 + kw)
                        * d_s[b * 128 + ci] * d_dc[b * 128 + co];
            v = __float2half_rn(val);
        }
        dst[idx] = v;
    }
}

// ---------------- main conv kernel ----------------
// smem: A [128 co][104 halfs] = 26624 B; B [96 k][136 halfs] = 26112 B
#define SM_A 0
#define SM_B 26624
#define SMEM_BYTES 52736

__global__ void __launch_bounds__(256, 2) k_conv(const float* __restrict__ x,
                                                 float* __restrict__ out) {
    extern __shared__ char smem[];
    uint32_t sb = smem_u32(smem);
    const int tid  = threadIdx.x;
    const int wid  = tid >> 5, lane = tid & 31;
    const int h = blockIdx.x, b = blockIdx.y;
    const int m0w = (wid & 3) * 32;     // warp m origin (co)
    const int n0w = (wid >> 2) * 64;    // warp n origin (w)

    float acc[2][8][4];
#pragma unroll
    for (int i = 0; i < 2; i++)
#pragma unroll
        for (int j = 0; j < 8; j++)
#pragma unroll
            for (int kq = 0; kq < 4; kq++) acc[i][j][kq] = 0.f;

    const float* xb = x + (size_t)b * CIN * HH * WW;
    const int ci_t = tid >> 3;   // 0..31 (ci within chunk for B build)
    const int sv   = tid & 7;

    // ldmatrix per-thread base addresses
    const uint32_t a_base = sb + SM_A + (uint32_t)(m0w + (lane & 15)) * 208
                            + (uint32_t)(lane >> 4) * 16;
    const uint32_t b_base = sb + SM_B + (uint32_t)(lane & 15) * 272
                            + (uint32_t)(n0w + (lane >> 4) * 8) * 2;

    for (int st = 0; st < 12; st++) {
        const int kh = st >> 2, chunk = st & 3;
        if (st) __syncthreads();

        // ---- A: async copy of pre-packed fp16 weights (26624 B) ----
        {
            const char* asrc = (const char*)(d_wA + (size_t)(b * 12 + st) * 13312);
#pragma unroll
            for (int i = 0; i < 7; i++) {
                int e = tid + i * 256;
                if (e < 1664)
                    CP_ASYNC16(sb + SM_A + (uint32_t)e * 16, asrc + (size_t)e * 16);
            }
            CP_COMMIT();
        }
        // ---- B: im2col, 3 shifted copies per ci row ----
        {
            const int hh = h + kh - 1;
            const bool rv = (hh >= 0) && (hh < HH);
            const float* xr = xb + ((size_t)(chunk * 32 + ci_t) * HH + (rv ? hh : 0)) * WW;
            const uint32_t brow = sb + SM_B + (uint32_t)(ci_t * 3) * 272;
#pragma unroll
            for (int i = 0; i < 17; i++) {
                int v = sv + 8 * i;           // 0..129 -> input w = v-1
                if (v < 130) {
                    int w = v - 1;
                    float f = 0.f;
                    if (rv && w >= 0 && w < WW) f = __ldg(xr + w);
                    unsigned short hv = __half_as_ushort(__float2half_rn(f));
#pragma unroll
                    for (int kw = 0; kw < 3; kw++) {
                        int n = v - kw;
                        if (n >= 0 && n < 128) {
                            uint32_t addr = brow + (uint32_t)kw * 272 + (uint32_t)(2 * n);
                            asm volatile("st.shared.b16 [%0], %1;" :: "r"(addr), "h"(hv));
                        }
                    }
                }
            }
        }
        CP_WAIT0();
        __syncthreads();

        // ---- compute: 6 k-steps of m16n8k16 ----
#pragma unroll
        for (int ks = 0; ks < 6; ks++) {
            uint32_t a0[4], a1[4], bf[4][4];
            LDSM4(a0, a_base + (uint32_t)ks * 32);
            LDSM4(a1, a_base + (uint32_t)ks * 32 + 16u * 208u);
#pragma unroll
            for (int nb = 0; nb < 4; nb++)
                LDSM4T(bf[nb], b_base + (uint32_t)ks * 16u * 272u + (uint32_t)nb * 32u);
#pragma unroll
            for (int mt = 0; mt < 2; mt++) {
                const uint32_t* a = mt ? a1 : a0;
#pragma unroll
                for (int nk = 0; nk < 8; nk++) {
                    uint32_t bb0 = bf[nk >> 1][(nk & 1) * 2];
                    uint32_t bb1 = bf[nk >> 1][(nk & 1) * 2 + 1];
                    mma16816(acc[mt][nk], a, bb0, bb1);
                }
            }
        }
    }

    // ---- epilogue ----
#pragma unroll
    for (int mt = 0; mt < 2; mt++) {
        int m_lo = m0w + mt * 16 + (lane >> 2);
#pragma unroll
        for (int nk = 0; nk < 8; nk++) {
            int n = n0w + nk * 8 + (lane & 3) * 2;
            float2 v0 = make_float2(acc[mt][nk][0], acc[mt][nk][1]);
            float2 v1 = make_float2(acc[mt][nk][2], acc[mt][nk][3]);
            *(float2*)(out + (((size_t)b * 128 + m_lo) * 128 + h) * 128 + n)     = v0;
            *(float2*)(out + (((size_t)b * 128 + m_lo + 8) * 128 + h) * 128 + n) = v1;
        }
    }
}

// ---------------- launch ----------------
extern "C" void kernel_launch(void* const* d_in, const int* in_sizes, int n_in,
                              void* d_out, int out_size) {
    const float* x      = (const float*)d_in[0];
    const float* style  = (const float*)d_in[1];
    const float* weight = (const float*)d_in[2];
    const float* mod_w  = (const float*)d_in[3];
    const float* mod_b  = (const float*)d_in[4];
    float* out = (float*)d_out;

    cudaFuncSetAttribute(k_conv, cudaFuncAttributeMaxDynamicSharedMemorySize, SMEM_BYTES);

    k_style<<<256, 256>>>(style, mod_w, mod_b);
    k_q<<<64, 256>>>(weight);
    k_dc<<<256, 256>>>();
    k_wprep<<<dim3(16, 12, 4), 256>>>(weight);
    dim3 grid(HH, BB);
    k_conv<<<grid, 256, SMEM_BYTES>>>(x, out);
}